// round 12
// baseline (speedup 1.0000x reference)
#include <cuda_runtime.h>
#include <cuda_bf16.h>
#include <math.h>

// ---------------- Problem dims ----------------
#define NL    8
#define BSZ   8
#define LSEQ  1024
#define DM    256
#define DI    512
#define NST   16
#define DTR   16
#define PROJC 48
#define MROWS (BSZ*LSEQ)  // 8192

// ---------------- Device scratch ----------------
__device__ float g_h   [MROWS*DM];
__device__ float g_xz  [MROWS*2*DI];
__device__ float g_proj[MROWS*PROJC];
__device__ float g_ymod[MROWS*DI];
__device__ float g_out2[MROWS*DM];
__device__ float g_pooled[BSZ*DM];

// ---------------- helpers ----------------
__device__ __forceinline__ void mma_tf32(float& d0, float& d1, float& d2, float& d3,
                                         unsigned a0, unsigned a1, unsigned a2, unsigned a3,
                                         unsigned b0, unsigned b1) {
    asm volatile(
        "mma.sync.aligned.m16n8k8.row.col.f32.tf32.tf32.f32 "
        "{%0,%1,%2,%3}, {%4,%5,%6,%7}, {%8,%9}, {%0,%1,%2,%3};\n"
        : "+f"(d0), "+f"(d1), "+f"(d2), "+f"(d3)
        : "r"(a0), "r"(a1), "r"(a2), "r"(a3), "r"(b0), "r"(b1));
}
__device__ __forceinline__ void cp16(unsigned dst, const void* src) {
    asm volatile("cp.async.cg.shared.global [%0], [%1], 16;\n" :: "r"(dst), "l"(src));
}
__device__ __forceinline__ void cp_commit() { asm volatile("cp.async.commit_group;\n"); }
__device__ __forceinline__ void cp_wait0()  { asm volatile("cp.async.wait_group 0;\n"); }
__device__ __forceinline__ void cp_wait1()  { asm volatile("cp.async.wait_group 1;\n"); }
__device__ __forceinline__ void cp_wait2()  { asm volatile("cp.async.wait_group 2;\n"); }

// ---------------- Encoder ----------------
__global__ void enc_kernel(const float* __restrict__ x,
                           const float* __restrict__ w,
                           const float* __restrict__ bb) {
    int bl = blockIdx.x;
    int m  = threadIdx.x;
    int b = bl >> 10, l = bl & 1023;
    float acc = bb[m];
#pragma unroll
    for (int c = 0; c < 3; c++)
        acc = fmaf(x[(b*3 + c)*LSEQ + l], w[c*DM + m], acc);
    g_h[bl*DM + m] = acc;
}

// ---------------- TF32 GEMM, cp.async 4-stage pipeline (in_proj / out_proj) -------
#define ASTR 20
#define BSTR 72
template<int BM>
__global__ void __launch_bounds__(256, 2)
gemm_tf32_cp(const float* __restrict__ A,
             const float* __restrict__ B,
             float* __restrict__ C,
             int M, int N, int K) {
    constexpr int AM = BM / 64;
    __shared__ unsigned As[4][BM*ASTR];
    __shared__ unsigned Bs[4][16*BSTR];

    const int tid  = threadIdx.x;
    const int lane = tid & 31;
    const int wid  = tid >> 5;
    const int wm   = wid & 3;
    const int wn   = wid >> 2;
    const int m0   = blockIdx.y * BM;
    const int n0   = blockIdx.x * 64;
    const int r = lane >> 2;
    const int c = lane & 3;

    const int bRow = tid >> 4;
    const int bNq  = tid & 15;
    const bool bOk = (n0 + bNq*4 + 3) < N;

    unsigned aBase[4], bBase[4];
#pragma unroll
    for (int s = 0; s < 4; s++) {
        aBase[s] = (unsigned)__cvta_generic_to_shared(&As[s][0]);
        bBase[s] = (unsigned)__cvta_generic_to_shared(&Bs[s][0]);
    }

    auto loadTile = [&](int t, int s) {
        int k0 = t * 16;
#pragma unroll
        for (int j = 0; j < AM; j++) {
            int slot = j*256 + tid;
            int row = slot >> 2, kq = slot & 3;
            cp16(aBase[s] + (row*ASTR + kq*4)*4,
                 A + (size_t)(m0 + row)*K + k0 + kq*4);
        }
        if (bOk)
            cp16(bBase[s] + (bRow*BSTR + bNq*4)*4,
                 B + (size_t)(k0 + bRow)*N + n0 + bNq*4);
        cp_commit();
    };

    float acc[AM][4][4] = {};
    const int T = K >> 4;

    loadTile(0, 0); loadTile(1, 1); loadTile(2, 2);

    for (int t = 0; t < T; t++) {
        int cur = t & 3;
        cp_wait2();
        __syncthreads();
        if (t + 3 < T) loadTile(t + 3, (t + 3) & 3);
        else           cp_commit();

        const unsigned* Ab = As[cur];
        const unsigned* Bb = Bs[cur];
#pragma unroll
        for (int kk = 0; kk < 16; kk += 8) {
            unsigned af[AM][4], bf[4][2];
#pragma unroll
            for (int am = 0; am < AM; am++) {
                int mrow = wm*(BM/4) + am*16;
                af[am][0] = Ab[(mrow + r    )*ASTR + kk + c    ];
                af[am][1] = Ab[(mrow + r + 8)*ASTR + kk + c    ];
                af[am][2] = Ab[(mrow + r    )*ASTR + kk + c + 4];
                af[am][3] = Ab[(mrow + r + 8)*ASTR + kk + c + 4];
            }
#pragma unroll
            for (int bn = 0; bn < 4; bn++) {
                int ncol = wn*32 + bn*8 + r;
                bf[bn][0] = Bb[(kk + c    )*BSTR + ncol];
                bf[bn][1] = Bb[(kk + c + 4)*BSTR + ncol];
            }
#pragma unroll
            for (int am = 0; am < AM; am++)
#pragma unroll
                for (int bn = 0; bn < 4; bn++)
                    mma_tf32(acc[am][bn][0], acc[am][bn][1], acc[am][bn][2], acc[am][bn][3],
                             af[am][0], af[am][1], af[am][2], af[am][3],
                             bf[bn][0], bf[bn][1]);
        }
    }

#pragma unroll
    for (int am = 0; am < AM; am++) {
#pragma unroll
        for (int bn = 0; bn < 4; bn++) {
            int m = m0 + wm*(BM/4) + am*16 + r;
            int n = n0 + wn*32 + bn*8 + 2*c;
            if (n + 1 < N) {
                *(float2*)(C + (size_t)m*N + n)       = make_float2(acc[am][bn][0], acc[am][bn][1]);
                *(float2*)(C + (size_t)(m + 8)*N + n) = make_float2(acc[am][bn][2], acc[am][bn][3]);
            } else if (n < N) {
                C[(size_t)m*N + n]       = acc[am][bn][0];
                C[(size_t)(m + 8)*N + n] = acc[am][bn][2];
            }
        }
    }
}

// ---------------- x_proj GEMM with fused conv+SiLU on the A path ----------------
#define RSTR 20
__global__ void __launch_bounds__(256)
xproj_conv_gemm(const float* __restrict__ xz,
                const float* __restrict__ W,
                float* __restrict__ Cout,
                const float* __restrict__ cw,
                const float* __restrict__ cb) {
    __shared__ unsigned As[64*RSTR];
    __shared__ float    Raw[3][67*RSTR];
    __shared__ unsigned Bs[3][16*BSTR];
    __shared__ float    scw[DI*4];
    __shared__ float    scb[DI];

    const int tid  = threadIdx.x;
    const int lane = tid & 31;
    const int wid  = tid >> 5;
    const int wm   = wid & 3;
    const int wn   = wid >> 2;
    const int m0   = blockIdx.y * 64;
    const int r = lane >> 2;
    const int c = lane & 3;

    for (int i = tid; i < 3*16*BSTR; i += 256) (&Bs[0][0])[i] = 0u;
    for (int i = tid; i < DI*4; i += 256) scw[i] = cw[i];
    for (int i = tid; i < DI;   i += 256) scb[i] = cb[i];
    const bool hz = (m0 & 1023) == 0;
    if (hz) {
#pragma unroll
        for (int s = 0; s < 3; s++)
            if (tid < 48) Raw[s][(tid >> 4)*RSTR + (tid & 15)] = 0.f;
    }
    __syncthreads();

    const int i1 = tid >> 2, q1 = tid & 3;
    const int bRow = tid >> 4;
    const int bNq  = tid & 15;
    const bool bOk = bNq < 12;

    unsigned rawB[3], bsB[3];
#pragma unroll
    for (int s = 0; s < 3; s++) {
        rawB[s] = (unsigned)__cvta_generic_to_shared(&Raw[s][0]);
        bsB[s]  = (unsigned)__cvta_generic_to_shared(&Bs[s][0]);
    }

    auto loadT = [&](int t, int s) {
        int k0 = t * 16;
        if (!hz || i1 >= 3)
            cp16(rawB[s] + (i1*RSTR + q1*4)*4,
                 xz + (size_t)(m0 - 3 + i1)*(2*DI) + k0 + q1*4);
        if (tid < 12) {
            int i2 = 64 + (tid >> 2);
            cp16(rawB[s] + (i2*RSTR + (tid & 3)*4)*4,
                 xz + (size_t)(m0 - 3 + i2)*(2*DI) + k0 + (tid & 3)*4);
        }
        if (bOk)
            cp16(bsB[s] + (bRow*BSTR + bNq*4)*4,
                 W + (size_t)(k0 + bRow)*PROJC + bNq*4);
        cp_commit();
    };

    float acc[4][4] = {};
    const int T = DI >> 4;

    loadT(0, 0); loadT(1, 1);

    for (int t = 0; t < T; t++) {
        int cur = t % 3;
        cp_wait1();
        __syncthreads();
        if (t + 2 < T) loadT(t + 2, (t + 2) % 3);
        else           cp_commit();

        {
            const float* R = Raw[cur];
            int row = tid >> 2;
            int cb4 = (tid & 3) * 4;
#pragma unroll
            for (int j = 0; j < 4; j++) {
                int cc = cb4 + j;
                int d  = t*16 + cc;
                float a = scb[d];
#pragma unroll
                for (int k = 0; k < 4; k++)
                    a = fmaf(R[(row + k)*RSTR + cc], scw[d*4 + k], a);
                a = a / (1.f + __expf(-a));
                As[row*RSTR + cc] = __float_as_uint(a);
            }
        }
        __syncthreads();

        const unsigned* Bb = Bs[cur];
#pragma unroll
        for (int kk = 0; kk < 16; kk += 8) {
            unsigned af[4], bf[4][2];
            {
                int mrow = wm*16;
                af[0] = As[(mrow + r    )*RSTR + kk + c    ];
                af[1] = As[(mrow + r + 8)*RSTR + kk + c    ];
                af[2] = As[(mrow + r    )*RSTR + kk + c + 4];
                af[3] = As[(mrow + r + 8)*RSTR + kk + c + 4];
            }
#pragma unroll
            for (int bn = 0; bn < 4; bn++) {
                int ncol = wn*32 + bn*8 + r;
                bf[bn][0] = Bb[(kk + c    )*BSTR + ncol];
                bf[bn][1] = Bb[(kk + c + 4)*BSTR + ncol];
            }
#pragma unroll
            for (int bn = 0; bn < 4; bn++)
                mma_tf32(acc[bn][0], acc[bn][1], acc[bn][2], acc[bn][3],
                         af[0], af[1], af[2], af[3],
                         bf[bn][0], bf[bn][1]);
        }
    }

#pragma unroll
    for (int bn = 0; bn < 4; bn++) {
        int m = m0 + wm*16 + r;
        int n = wn*32 + bn*8 + 2*c;
        if (n + 1 < PROJC) {
            *(float2*)(Cout + (size_t)m*PROJC + n)       = make_float2(acc[bn][0], acc[bn][1]);
            *(float2*)(Cout + (size_t)(m + 8)*PROJC + n) = make_float2(acc[bn][2], acc[bn][3]);
        } else if (n < PROJC) {
            Cout[(size_t)m*PROJC + n]       = acc[bn][0];
            Cout[(size_t)(m + 8)*PROJC + n] = acc[bn][2];
        }
    }
}

// ---------------- Fused conv + dt + scan, deferred reduction ----------------
// Block = 256 thr = 16 halfwarp channels. Chunks of 32 steps.
// Serial loop ONLY updates state and stashes it in SMEM (ps); the
// sum-over-n, D-skip and gating happen in a parallel phase per chunk.
#define SCH 32
#define SPSTR 52
#define PSL 288   // per-l stride in ps: 16 n * 18
__global__ void __launch_bounds__(256)
scan_kernel(const float* __restrict__ A_log,
            const float* __restrict__ Dv,
            const float* __restrict__ dtw,
            const float* __restrict__ dtb,
            const float* __restrict__ cw,
            const float* __restrict__ cb) {
    __shared__ float sp[2][SCH*SPSTR];    // proj rows       13.3 KB
    __shared__ float rx[2][35*16];        // raw x + halo     4.5 KB
    __shared__ float sz[2][SCH*16];       // z -> gate        4.1 KB
    __shared__ float su2[SCH*16];         // u; reused as y   2.0 KB
    __shared__ float ps[SCH*PSL];         // state stash     36.9 KB
    __shared__ float sDv[16];

    const int b  = blockIdx.x >> 5;
    const int d0 = (blockIdx.x & 31) * 16;
    const int tid = threadIdx.x;
    const int hw = tid >> 4;
    const int n  = tid & 15;
    const int d  = d0 + hw;
    const int lane = tid & 31;
    const int hbase = lane & 16;
    const int blbase = b << 10;

    // conv weights: 2 convert columns per thread (row = tid>>3, cols (tid&7)*2..+1)
    const int cvrow = tid >> 3;
    const int ccol  = (tid & 7) * 2;
    float wv[2][4], bv[2];
#pragma unroll
    for (int j = 0; j < 2; j++) {
        bv[j] = cb[d0 + ccol + j];
#pragma unroll
        for (int k = 0; k < 4; k++)
            wv[j][k] = cw[(d0 + ccol + j)*4 + k];
    }
    if (tid < 16) sDv[tid] = Dv[d0 + tid];
    if (tid < 48) rx[0][tid] = 0.f;   // chunk-0 halo

    unsigned spB[2], rxB[2], szB[2];
#pragma unroll
    for (int s = 0; s < 2; s++) {
        spB[s] = (unsigned)__cvta_generic_to_shared(&sp[s][0]);
        rxB[s] = (unsigned)__cvta_generic_to_shared(&rx[s][0]);
        szB[s] = (unsigned)__cvta_generic_to_shared(&sz[s][0]);
    }

    auto loadChunk = [&](int c0, int buf) {
        // raw x rows c0-3 .. c0+31 (35 rows x 16 cols = 140 slots of 16B)
        if (tid < 140) {
            int row = tid >> 2, q = tid & 3;
            if (c0 != 0 || row >= 3)
                cp16(rxB[buf] + (row*16 + q*4)*4,
                     g_xz + (size_t)(blbase + c0 - 3 + row)*(2*DI) + d0 + q*4);
        }
        // z rows (128 slots)
        if (tid < 128) {
            int row = tid >> 2, q = tid & 3;
            cp16(szB[buf] + (row*16 + q*4)*4,
                 g_xz + (size_t)(blbase + c0 + row)*(2*DI) + DI + d0 + q*4);
        }
        // proj rows (32*12 = 384 slots)
        {
            int s0 = tid;
            int l = s0 / 12, q = s0 - l*12;
            cp16(spB[buf] + (l*SPSTR + q*4)*4,
                 g_proj + (size_t)(blbase + c0 + l)*PROJC + q*4);
            int s1 = tid + 256;
            if (s1 < 384) {
                int l1 = s1 / 12, q1 = s1 - l1*12;
                cp16(spB[buf] + (l1*SPSTR + q1*4)*4,
                     g_proj + (size_t)(blbase + c0 + l1)*PROJC + q1*4);
            }
        }
        cp_commit();
    };

    float wdt[DTR];
#pragma unroll
    for (int r = 0; r < DTR; r++) wdt[r] = dtw[r*DI + d];
    const float dtbv = dtb[d];
    const float Ad = -__expf(A_log[d*NST + n]);
    float state = 0.f;

    loadChunk(0, 0);

    const int NCH = LSEQ / SCH;   // 32
    for (int cc = 0; cc < NCH; cc++) {
        int buf = cc & 1;
        if (cc + 1 < NCH) { loadChunk((cc+1)*SCH, buf ^ 1); cp_wait1(); }
        else              { cp_wait0(); }
        __syncthreads();

        const float* P = sp[buf];
        const float* X = rx[buf];
        float*       Z = sz[buf];

        // dt for steps {j*16+n}
        float dtv2[2];
#pragma unroll
        for (int j = 0; j < 2; j++) {
            float a = dtbv;
            const float* row = &P[(j*16 + n)*SPSTR];
#pragma unroll
            for (int r = 0; r < DTR; r++) a = fmaf(row[r], wdt[r], a);
            dtv2[j] = (a > 20.f) ? a : __logf(1.f + __expf(a));
        }

        // convert: u = silu(conv(x)); gate = silu(z)  (2 cols per thread)
#pragma unroll
        for (int j = 0; j < 2; j++) {
            int c2 = ccol + j;
            float a = bv[j];
#pragma unroll
            for (int k = 0; k < 4; k++)
                a = fmaf(X[(cvrow + k)*16 + c2], wv[j][k], a);
            su2[cvrow*16 + c2] = a / (1.f + __expf(-a));
            float zz = Z[cvrow*16 + c2];
            Z[cvrow*16 + c2] = zz / (1.f + __expf(-zz));
        }
        __syncthreads();

        // lean serial loop: state update + stash only
#pragma unroll 8
        for (int l = 0; l < SCH; l++) {
            float dtv = __shfl_sync(0xffffffffu, dtv2[l >> 4], hbase + (l & 15), 32);
            float uv = su2[l*16 + hw];
            float Bv = P[l*SPSTR + DTR + n];
            state = fmaf(__expf(dtv*Ad), state, dtv*uv*Bv);
            ps[l*PSL + n*18 + hw] = state;
        }
        __syncthreads();

        // parallel reduction: y = (sum_n state*C + u*D) * gate  (2 tasks/thread)
#pragma unroll
        for (int t2 = tid; t2 < SCH*16; t2 += 256) {
            int l  = t2 >> 4;
            int d2 = t2 & 15;
            const float* prow = &ps[l*PSL + d2];
            const float* crow = &P[l*SPSTR + DTR + NST];
            float acc = 0.f;
#pragma unroll
            for (int n2 = 0; n2 < 16; n2++)
                acc = fmaf(prow[n2*18], crow[n2], acc);
            float uv = su2[l*16 + d2];
            su2[l*16 + d2] = (acc + uv*sDv[d2]) * Z[l*16 + d2];
        }
        __syncthreads();

        // coalesced writeback (32 rows x 16 cols = 128 float4)
        if (tid < 128) {
            int row = tid >> 2, q = tid & 3;
            float4 v = *(const float4*)&su2[row*16 + q*4];
            *(float4*)(g_ymod + (size_t)(blbase + cc*SCH + row)*DI + d0 + q*4) = v;
        }
        __syncthreads();
    }
}

// ---------------- Residual add + LayerNorm: warp-per-row, float4 ----------------
__global__ void __launch_bounds__(512)
ln_kernel(const float* __restrict__ gamma,
          const float* __restrict__ beta) {
    int wid  = threadIdx.x >> 5;
    int lane = threadIdx.x & 31;
    int bl   = blockIdx.x * 16 + wid;
    int col  = lane * 8;

    const float4* o4 = (const float4*)(g_out2 + (size_t)bl*DM + col);
    const float4* h4 = (const float4*)(g_h    + (size_t)bl*DM + col);
    float t[8];
    float4 a = o4[0], b = h4[0];
    t[0]=a.x+b.x; t[1]=a.y+b.y; t[2]=a.z+b.z; t[3]=a.w+b.w;
    a = o4[1]; b = h4[1];
    t[4]=a.x+b.x; t[5]=a.y+b.y; t[6]=a.z+b.z; t[7]=a.w+b.w;

    float v1 = 0.f, v2 = 0.f;
#pragma unroll
    for (int i = 0; i < 8; i++) { v1 += t[i]; v2 = fmaf(t[i], t[i], v2); }
#pragma unroll
    for (int o = 16; o > 0; o >>= 1) {
        v1 += __shfl_xor_sync(0xffffffffu, v1, o);
        v2 += __shfl_xor_sync(0xffffffffu, v2, o);
    }
    float mean = v1 * (1.f/DM);
    float var  = v2 * (1.f/DM) - mean*mean;
    float rs = rsqrtf(var + 1e-5f);

    float4 g0 = *(const float4*)(gamma + col);
    float4 g1 = *(const float4*)(gamma + col + 4);
    float4 b0 = *(const float4*)(beta  + col);
    float4 b1 = *(const float4*)(beta  + col + 4);

    float4 r0, r1;
    r0.x = (t[0]-mean)*rs*g0.x + b0.x;
    r0.y = (t[1]-mean)*rs*g0.y + b0.y;
    r0.z = (t[2]-mean)*rs*g0.z + b0.z;
    r0.w = (t[3]-mean)*rs*g0.w + b0.w;
    r1.x = (t[4]-mean)*rs*g1.x + b1.x;
    r1.y = (t[5]-mean)*rs*g1.y + b1.y;
    r1.z = (t[6]-mean)*rs*g1.z + b1.z;
    r1.w = (t[7]-mean)*rs*g1.w + b1.w;

    float4* out4 = (float4*)(g_h + (size_t)bl*DM + col);
    out4[0] = r0;
    out4[1] = r1;
}

// ---------------- Mean pool ----------------
__global__ void pool_kernel() {
    int b = blockIdx.x;
    int m = threadIdx.x;
    float s = 0.f;
    for (int l = 0; l < LSEQ; l++)
        s += g_h[(size_t)((b << 10) + l)*DM + m];
    g_pooled[b*DM + m] = s * (1.f/LSEQ);
}

// ---------------- Decoder ----------------
__global__ void dec_kernel(const float* __restrict__ w,
                           const float* __restrict__ bb,
                           float* __restrict__ out) {
    int i = threadIdx.x;
    if (i < BSZ*10) {
        int b = i / 10, o = i % 10;
        float acc = bb[o];
#pragma unroll 8
        for (int m = 0; m < DM; m++)
            acc = fmaf(g_pooled[b*DM + m], w[m*10 + o], acc);
        out[i] = acc;
    }
}

// ---------------- Launch ----------------
extern "C" void kernel_launch(void* const* d_in, const int* in_sizes, int n_in,
                              void* d_out, int out_size) {
    const float* x         = (const float*)d_in[0];
    const float* enc_w     = (const float*)d_in[1];
    const float* enc_b     = (const float*)d_in[2];
    const float* in_proj_w = (const float*)d_in[3];
    const float* conv_w    = (const float*)d_in[4];
    const float* conv_b    = (const float*)d_in[5];
    const float* x_proj_w  = (const float*)d_in[6];
    const float* dt_w      = (const float*)d_in[7];
    const float* dt_b      = (const float*)d_in[8];
    const float* A_log     = (const float*)d_in[9];
    const float* Dv        = (const float*)d_in[10];
    const float* out_proj_w= (const float*)d_in[11];
    const float* ln_g      = (const float*)d_in[12];
    const float* ln_b      = (const float*)d_in[13];
    const float* dec_w     = (const float*)d_in[14];
    const float* dec_b     = (const float*)d_in[15];

    float *p_h, *p_xz, *p_proj, *p_ymod, *p_out2;
    cudaGetSymbolAddress((void**)&p_h,    g_h);
    cudaGetSymbolAddress((void**)&p_xz,   g_xz);
    cudaGetSymbolAddress((void**)&p_proj, g_proj);
    cudaGetSymbolAddress((void**)&p_ymod, g_ymod);
    cudaGetSymbolAddress((void**)&p_out2, g_out2);

    enc_kernel<<<MROWS, DM>>>(x, enc_w, enc_b);

    for (int i = 0; i < NL; i++) {
        // xz = h @ in_proj_w[i]   (8192x256 @ 256x1024)
        gemm_tf32_cp<128><<<dim3((2*DI)/64, MROWS/128), 256>>>(
            p_h, in_proj_w + (size_t)i*DM*2*DI, p_xz, MROWS, 2*DI, DM);

        // proj = silu(conv(xz_x)) @ x_proj_w[i]  (conv fused into A staging)
        xproj_conv_gemm<<<dim3(1, MROWS/64), 256>>>(
            p_xz, x_proj_w + (size_t)i*DI*PROJC, p_proj,
            conv_w + (size_t)i*DI*4, conv_b + (size_t)i*DI);

        // fused conv + dt + scan (deferred reduction)
        scan_kernel<<<BSZ*32, 256>>>(A_log + (size_t)i*DI*NST, Dv + (size_t)i*DI,
                                     dt_w + (size_t)i*DTR*DI, dt_b + (size_t)i*DI,
                                     conv_w + (size_t)i*DI*4, conv_b + (size_t)i*DI);

        // out2 = ymod @ out_proj_w[i]  (8192x512 @ 512x256)
        gemm_tf32_cp<128><<<dim3(DM/64, MROWS/128), 256>>>(
            p_ymod, out_proj_w + (size_t)i*DI*DM, p_out2, MROWS, DM, DI);

        // h = layernorm(out2 + h)
        ln_kernel<<<MROWS/16, 512>>>(ln_g + (size_t)i*DM, ln_b + (size_t)i*DM);
    }

    pool_kernel<<<BSZ, DM>>>();
    dec_kernel<<<1, 128>>>(dec_w, dec_b, (float*)d_out);
}

// round 13
// speedup vs baseline: 1.2622x; 1.2622x over previous
#include <cuda_runtime.h>
#include <cuda_bf16.h>
#include <math.h>

// ---------------- Problem dims ----------------
#define NL    8
#define BSZ   8
#define LSEQ  1024
#define DM    256
#define DI    512
#define NST   16
#define DTR   16
#define PROJC 48
#define MROWS (BSZ*LSEQ)  // 8192

// ---------------- Device scratch ----------------
__device__ float g_h   [MROWS*DM];
__device__ float g_xz  [MROWS*2*DI];
__device__ float g_proj[MROWS*PROJC];
__device__ float g_ymod[MROWS*DI];
__device__ float g_out2[MROWS*DM];
__device__ float g_pooled[BSZ*DM];

// ---------------- helpers ----------------
__device__ __forceinline__ void mma_tf32(float& d0, float& d1, float& d2, float& d3,
                                         unsigned a0, unsigned a1, unsigned a2, unsigned a3,
                                         unsigned b0, unsigned b1) {
    asm volatile(
        "mma.sync.aligned.m16n8k8.row.col.f32.tf32.tf32.f32 "
        "{%0,%1,%2,%3}, {%4,%5,%6,%7}, {%8,%9}, {%0,%1,%2,%3};\n"
        : "+f"(d0), "+f"(d1), "+f"(d2), "+f"(d3)
        : "r"(a0), "r"(a1), "r"(a2), "r"(a3), "r"(b0), "r"(b1));
}
__device__ __forceinline__ void cp16(unsigned dst, const void* src) {
    asm volatile("cp.async.cg.shared.global [%0], [%1], 16;\n" :: "r"(dst), "l"(src));
}
__device__ __forceinline__ void cp_commit() { asm volatile("cp.async.commit_group;\n"); }
__device__ __forceinline__ void cp_wait0()  { asm volatile("cp.async.wait_group 0;\n"); }
__device__ __forceinline__ void cp_wait1()  { asm volatile("cp.async.wait_group 1;\n"); }
__device__ __forceinline__ void cp_wait2()  { asm volatile("cp.async.wait_group 2;\n"); }

// ---------------- Encoder ----------------
__global__ void enc_kernel(const float* __restrict__ x,
                           const float* __restrict__ w,
                           const float* __restrict__ bb) {
    int bl = blockIdx.x;
    int m  = threadIdx.x;
    int b = bl >> 10, l = bl & 1023;
    float acc = bb[m];
#pragma unroll
    for (int c = 0; c < 3; c++)
        acc = fmaf(x[(b*3 + c)*LSEQ + l], w[c*DM + m], acc);
    g_h[bl*DM + m] = acc;
}

// ---------------- TF32 GEMM, cp.async 4-stage pipeline (in_proj / out_proj) -------
#define ASTR 20
#define BSTR 72
template<int BM>
__global__ void __launch_bounds__(256, 2)
gemm_tf32_cp(const float* __restrict__ A,
             const float* __restrict__ B,
             float* __restrict__ C,
             int M, int N, int K) {
    constexpr int AM = BM / 64;
    __shared__ unsigned As[4][BM*ASTR];
    __shared__ unsigned Bs[4][16*BSTR];

    const int tid  = threadIdx.x;
    const int lane = tid & 31;
    const int wid  = tid >> 5;
    const int wm   = wid & 3;
    const int wn   = wid >> 2;
    const int m0   = blockIdx.y * BM;
    const int n0   = blockIdx.x * 64;
    const int r = lane >> 2;
    const int c = lane & 3;

    const int bRow = tid >> 4;
    const int bNq  = tid & 15;
    const bool bOk = (n0 + bNq*4 + 3) < N;

    unsigned aBase[4], bBase[4];
#pragma unroll
    for (int s = 0; s < 4; s++) {
        aBase[s] = (unsigned)__cvta_generic_to_shared(&As[s][0]);
        bBase[s] = (unsigned)__cvta_generic_to_shared(&Bs[s][0]);
    }

    auto loadTile = [&](int t, int s) {
        int k0 = t * 16;
#pragma unroll
        for (int j = 0; j < AM; j++) {
            int slot = j*256 + tid;
            int row = slot >> 2, kq = slot & 3;
            cp16(aBase[s] + (row*ASTR + kq*4)*4,
                 A + (size_t)(m0 + row)*K + k0 + kq*4);
        }
        if (bOk)
            cp16(bBase[s] + (bRow*BSTR + bNq*4)*4,
                 B + (size_t)(k0 + bRow)*N + n0 + bNq*4);
        cp_commit();
    };

    float acc[AM][4][4] = {};
    const int T = K >> 4;

    loadTile(0, 0); loadTile(1, 1); loadTile(2, 2);

    for (int t = 0; t < T; t++) {
        int cur = t & 3;
        cp_wait2();
        __syncthreads();
        if (t + 3 < T) loadTile(t + 3, (t + 3) & 3);
        else           cp_commit();

        const unsigned* Ab = As[cur];
        const unsigned* Bb = Bs[cur];
#pragma unroll
        for (int kk = 0; kk < 16; kk += 8) {
            unsigned af[AM][4], bf[4][2];
#pragma unroll
            for (int am = 0; am < AM; am++) {
                int mrow = wm*(BM/4) + am*16;
                af[am][0] = Ab[(mrow + r    )*ASTR + kk + c    ];
                af[am][1] = Ab[(mrow + r + 8)*ASTR + kk + c    ];
                af[am][2] = Ab[(mrow + r    )*ASTR + kk + c + 4];
                af[am][3] = Ab[(mrow + r + 8)*ASTR + kk + c + 4];
            }
#pragma unroll
            for (int bn = 0; bn < 4; bn++) {
                int ncol = wn*32 + bn*8 + r;
                bf[bn][0] = Bb[(kk + c    )*BSTR + ncol];
                bf[bn][1] = Bb[(kk + c + 4)*BSTR + ncol];
            }
#pragma unroll
            for (int am = 0; am < AM; am++)
#pragma unroll
                for (int bn = 0; bn < 4; bn++)
                    mma_tf32(acc[am][bn][0], acc[am][bn][1], acc[am][bn][2], acc[am][bn][3],
                             af[am][0], af[am][1], af[am][2], af[am][3],
                             bf[bn][0], bf[bn][1]);
        }
    }

#pragma unroll
    for (int am = 0; am < AM; am++) {
#pragma unroll
        for (int bn = 0; bn < 4; bn++) {
            int m = m0 + wm*(BM/4) + am*16 + r;
            int n = n0 + wn*32 + bn*8 + 2*c;
            if (n + 1 < N) {
                *(float2*)(C + (size_t)m*N + n)       = make_float2(acc[am][bn][0], acc[am][bn][1]);
                *(float2*)(C + (size_t)(m + 8)*N + n) = make_float2(acc[am][bn][2], acc[am][bn][3]);
            } else if (n < N) {
                C[(size_t)m*N + n]       = acc[am][bn][0];
                C[(size_t)(m + 8)*N + n] = acc[am][bn][2];
            }
        }
    }
}

// ---------------- x_proj GEMM with fused conv+SiLU on the A path ----------------
#define RSTR 20
__global__ void __launch_bounds__(256)
xproj_conv_gemm(const float* __restrict__ xz,
                const float* __restrict__ W,
                float* __restrict__ Cout,
                const float* __restrict__ cw,
                const float* __restrict__ cb) {
    __shared__ unsigned As[64*RSTR];
    __shared__ float    Raw[3][67*RSTR];
    __shared__ unsigned Bs[3][16*BSTR];
    __shared__ float    scw[DI*4];
    __shared__ float    scb[DI];

    const int tid  = threadIdx.x;
    const int lane = tid & 31;
    const int wid  = tid >> 5;
    const int wm   = wid & 3;
    const int wn   = wid >> 2;
    const int m0   = blockIdx.y * 64;
    const int r = lane >> 2;
    const int c = lane & 3;

    for (int i = tid; i < 3*16*BSTR; i += 256) (&Bs[0][0])[i] = 0u;
    for (int i = tid; i < DI*4; i += 256) scw[i] = cw[i];
    for (int i = tid; i < DI;   i += 256) scb[i] = cb[i];
    const bool hz = (m0 & 1023) == 0;
    if (hz) {
#pragma unroll
        for (int s = 0; s < 3; s++)
            if (tid < 48) Raw[s][(tid >> 4)*RSTR + (tid & 15)] = 0.f;
    }
    __syncthreads();

    const int i1 = tid >> 2, q1 = tid & 3;
    const int bRow = tid >> 4;
    const int bNq  = tid & 15;
    const bool bOk = bNq < 12;

    unsigned rawB[3], bsB[3];
#pragma unroll
    for (int s = 0; s < 3; s++) {
        rawB[s] = (unsigned)__cvta_generic_to_shared(&Raw[s][0]);
        bsB[s]  = (unsigned)__cvta_generic_to_shared(&Bs[s][0]);
    }

    auto loadT = [&](int t, int s) {
        int k0 = t * 16;
        if (!hz || i1 >= 3)
            cp16(rawB[s] + (i1*RSTR + q1*4)*4,
                 xz + (size_t)(m0 - 3 + i1)*(2*DI) + k0 + q1*4);
        if (tid < 12) {
            int i2 = 64 + (tid >> 2);
            cp16(rawB[s] + (i2*RSTR + (tid & 3)*4)*4,
                 xz + (size_t)(m0 - 3 + i2)*(2*DI) + k0 + (tid & 3)*4);
        }
        if (bOk)
            cp16(bsB[s] + (bRow*BSTR + bNq*4)*4,
                 W + (size_t)(k0 + bRow)*PROJC + bNq*4);
        cp_commit();
    };

    float acc[4][4] = {};
    const int T = DI >> 4;

    loadT(0, 0); loadT(1, 1);

    for (int t = 0; t < T; t++) {
        int cur = t % 3;
        cp_wait1();
        __syncthreads();
        if (t + 2 < T) loadT(t + 2, (t + 2) % 3);
        else           cp_commit();

        {
            const float* R = Raw[cur];
            int row = tid >> 2;
            int cb4 = (tid & 3) * 4;
#pragma unroll
            for (int j = 0; j < 4; j++) {
                int cc = cb4 + j;
                int d  = t*16 + cc;
                float a = scb[d];
#pragma unroll
                for (int k = 0; k < 4; k++)
                    a = fmaf(R[(row + k)*RSTR + cc], scw[d*4 + k], a);
                a = a / (1.f + __expf(-a));
                As[row*RSTR + cc] = __float_as_uint(a);
            }
        }
        __syncthreads();

        const unsigned* Bb = Bs[cur];
#pragma unroll
        for (int kk = 0; kk < 16; kk += 8) {
            unsigned af[4], bf[4][2];
            {
                int mrow = wm*16;
                af[0] = As[(mrow + r    )*RSTR + kk + c    ];
                af[1] = As[(mrow + r + 8)*RSTR + kk + c    ];
                af[2] = As[(mrow + r    )*RSTR + kk + c + 4];
                af[3] = As[(mrow + r + 8)*RSTR + kk + c + 4];
            }
#pragma unroll
            for (int bn = 0; bn < 4; bn++) {
                int ncol = wn*32 + bn*8 + r;
                bf[bn][0] = Bb[(kk + c    )*BSTR + ncol];
                bf[bn][1] = Bb[(kk + c + 4)*BSTR + ncol];
            }
#pragma unroll
            for (int bn = 0; bn < 4; bn++)
                mma_tf32(acc[bn][0], acc[bn][1], acc[bn][2], acc[bn][3],
                         af[0], af[1], af[2], af[3],
                         bf[bn][0], bf[bn][1]);
        }
    }

#pragma unroll
    for (int bn = 0; bn < 4; bn++) {
        int m = m0 + wm*16 + r;
        int n = wn*32 + bn*8 + 2*c;
        if (n + 1 < PROJC) {
            *(float2*)(Cout + (size_t)m*PROJC + n)       = make_float2(acc[bn][0], acc[bn][1]);
            *(float2*)(Cout + (size_t)(m + 8)*PROJC + n) = make_float2(acc[bn][2], acc[bn][3]);
        } else if (n < PROJC) {
            Cout[(size_t)m*PROJC + n]       = acc[bn][0];
            Cout[(size_t)(m + 8)*PROJC + n] = acc[bn][2];
        }
    }
}

// ---------------- Fused conv + dt + scan, lean serial loop ----------------
// Block = 256 thr = 16 halfwarp channels. SCH=64 chunks (same barrier count
// as the 2184us kernel). Convert phase additionally builds:
//   sBC[l][n] = {B, C} pairs           (1 LDS.64/step instead of 2 LDS)
//   sgg[l][hw] = {gate, u*D*gate} pairs (pred tail = LDS.64+FFMA+STS)
#define SCH 64
#define SPSTR 52
__global__ void __launch_bounds__(256)
scan_kernel(const float* __restrict__ A_log,
            const float* __restrict__ Dv,
            const float* __restrict__ dtw,
            const float* __restrict__ dtb,
            const float* __restrict__ cw,
            const float* __restrict__ cb) {
    __shared__ float sp[2][SCH*SPSTR];   // proj rows        26.6 KB
    __shared__ float rx[2][67*16];       // raw x + halo      8.6 KB
    __shared__ float sz[2][SCH*16];      // raw z             8.2 KB
    __shared__ float su2[SCH*16];        // u; reused as y    4.1 KB
    __shared__ float sBC[SCH*32];        // B,C pairs         8.2 KB
    __shared__ float sgg[SCH*32];        // gate, u*D*gate    8.2 KB
    __shared__ float sDv[16];

    const int b  = blockIdx.x >> 5;
    const int d0 = (blockIdx.x & 31) * 16;
    const int tid = threadIdx.x;
    const int hw = tid >> 4;
    const int n  = tid & 15;
    const int d  = d0 + hw;
    const int lane = tid & 31;
    const int hbase = lane & 16;
    const int blbase = b << 10;

    const int rl = tid >> 2;
    const int rq = tid & 3;

    // conv weights for this thread's 4 convert columns
    const int ccol = (tid & 3) * 4;
    float wv[4][4], bv[4];
#pragma unroll
    for (int j = 0; j < 4; j++) {
        bv[j] = cb[d0 + ccol + j];
#pragma unroll
        for (int k = 0; k < 4; k++)
            wv[j][k] = cw[(d0 + ccol + j)*4 + k];
    }
    if (tid < 16) sDv[tid] = Dv[d0 + tid];
    if (tid < 48) rx[0][tid] = 0.f;   // chunk-0 halo

    unsigned spB[2], rxB[2], szB[2];
#pragma unroll
    for (int s = 0; s < 2; s++) {
        spB[s] = (unsigned)__cvta_generic_to_shared(&sp[s][0]);
        rxB[s] = (unsigned)__cvta_generic_to_shared(&rx[s][0]);
        szB[s] = (unsigned)__cvta_generic_to_shared(&sz[s][0]);
    }

    auto loadChunk = [&](int c0, int buf) {
        cp16(rxB[buf] + (rl*16 + rq*4)*4 + 48*4*0,
             g_xz + (size_t)(blbase + c0 - 3 + rl)*(2*DI) + d0 + rq*4);
        if (tid < 12) {
            int i2 = 64 + (tid >> 2);
            cp16(rxB[buf] + (i2*16 + (tid & 3)*4)*4,
                 g_xz + (size_t)(blbase + c0 - 3 + i2)*(2*DI) + d0 + (tid & 3)*4);
        }
        cp16(szB[buf] + (rl*16 + rq*4)*4,
             g_xz + (size_t)(blbase + c0 + rl)*(2*DI) + DI + d0 + rq*4);
#pragma unroll
        for (int k = 0; k < 3; k++) {
            int s = tid + k*256;
            int l = s / 12, q = s - l*12;
            cp16(spB[buf] + (l*SPSTR + q*4)*4,
                 g_proj + (size_t)(blbase + c0 + l)*PROJC + q*4);
        }
        cp_commit();
    };
    // chunk-0: skip the 3 halo rows (they're zeroed)
    auto loadChunk0 = [&]() {
        if (rl >= 3)
            cp16(rxB[0] + (rl*16 + rq*4)*4,
                 g_xz + (size_t)(blbase - 3 + rl)*(2*DI) + d0 + rq*4);
        if (tid < 12) {
            int i2 = 64 + (tid >> 2);
            cp16(rxB[0] + (i2*16 + (tid & 3)*4)*4,
                 g_xz + (size_t)(blbase - 3 + i2)*(2*DI) + d0 + (tid & 3)*4);
        }
        cp16(szB[0] + (rl*16 + rq*4)*4,
             g_xz + (size_t)(blbase + rl)*(2*DI) + DI + d0 + rq*4);
#pragma unroll
        for (int k = 0; k < 3; k++) {
            int s = tid + k*256;
            int l = s / 12, q = s - l*12;
            cp16(spB[0] + (l*SPSTR + q*4)*4,
                 g_proj + (size_t)(blbase + l)*PROJC + q*4);
        }
        cp_commit();
    };

    float wdt[DTR];
#pragma unroll
    for (int r = 0; r < DTR; r++) wdt[r] = dtw[r*DI + d];
    const float dtbv = dtb[d];
    const float Ad = -__expf(A_log[d*NST + n]);
    float state = 0.f;

    loadChunk0();

    for (int cc = 0; cc < LSEQ/SCH; cc++) {
        int buf = cc & 1;
        if (cc + 1 < LSEQ/SCH) { loadChunk((cc+1)*SCH, buf ^ 1); cp_wait1(); }
        else                   { cp_wait0(); }
        __syncthreads();

        const float* P = sp[buf];
        const float* X = rx[buf];
        const float* Z = sz[buf];

        // dt for steps {j*16+n}
        float dtv4[4];
#pragma unroll
        for (int j = 0; j < 4; j++) {
            float a = dtbv;
            const float* row = &P[(j*16 + n)*SPSTR];
#pragma unroll
            for (int r = 0; r < DTR; r++) a = fmaf(row[r], wdt[r], a);
            dtv4[j] = (a > 20.f) ? a : __logf(1.f + __expf(a));
        }

        // convert: u, gate, g2 = u*D*gate  (4 cols per thread at row rl)
#pragma unroll
        for (int j = 0; j < 4; j++) {
            int c2 = ccol + j;
            float a = bv[j];
#pragma unroll
            for (int k = 0; k < 4; k++)
                a = fmaf(X[(rl + k)*16 + c2], wv[j][k], a);
            float u = a / (1.f + __expf(-a));
            su2[rl*16 + c2] = u;
            float zz = Z[rl*16 + c2];
            float gate = zz / (1.f + __expf(-zz));
            sgg[rl*32 + c2*2    ] = gate;
            sgg[rl*32 + c2*2 + 1] = u * sDv[c2] * gate;
        }
        // B/C pairing (4 per thread)
#pragma unroll
        for (int t2 = tid; t2 < SCH*16; t2 += 256) {
            int l  = t2 >> 4;
            int n2 = t2 & 15;
            float Bv = P[l*SPSTR + DTR + n2];
            float Cv = P[l*SPSTR + DTR + NST + n2];
            *(float2*)&sBC[l*32 + n2*2] = make_float2(Bv, Cv);
        }
        __syncthreads();

        // lean serial loop
#pragma unroll 4
        for (int l = 0; l < SCH; l++) {
            float dtv = __shfl_sync(0xffffffffu, dtv4[l >> 4], hbase + (l & 15), 32);
            float uv  = su2[l*16 + hw];
            float2 bc = *(const float2*)&sBC[l*32 + n*2];
            state = fmaf(__expf(dtv*Ad), state, dtv*uv*bc.x);
            float p = state * bc.y;
            p += __shfl_xor_sync(0xffffffffu, p, 8);
            p += __shfl_xor_sync(0xffffffffu, p, 4);
            p += __shfl_xor_sync(0xffffffffu, p, 2);
            p += __shfl_xor_sync(0xffffffffu, p, 1);
            if (n == 0) {
                float2 gg = *(const float2*)&sgg[l*32 + hw*2];
                su2[l*16 + hw] = fmaf(p, gg.x, gg.y);
            }
        }
        __syncthreads();

        // coalesced writeback
        {
            float4 v = *(const float4*)&su2[rl*16 + rq*4];
            *(float4*)(g_ymod + (size_t)(blbase + cc*SCH + rl)*DI + d0 + rq*4) = v;
        }
    }
}

// ---------------- Residual add + LayerNorm: warp-per-row, float4 ----------------
__global__ void __launch_bounds__(512)
ln_kernel(const float* __restrict__ gamma,
          const float* __restrict__ beta) {
    int wid  = threadIdx.x >> 5;
    int lane = threadIdx.x & 31;
    int bl   = blockIdx.x * 16 + wid;
    int col  = lane * 8;

    const float4* o4 = (const float4*)(g_out2 + (size_t)bl*DM + col);
    const float4* h4 = (const float4*)(g_h    + (size_t)bl*DM + col);
    float t[8];
    float4 a = o4[0], b = h4[0];
    t[0]=a.x+b.x; t[1]=a.y+b.y; t[2]=a.z+b.z; t[3]=a.w+b.w;
    a = o4[1]; b = h4[1];
    t[4]=a.x+b.x; t[5]=a.y+b.y; t[6]=a.z+b.z; t[7]=a.w+b.w;

    float v1 = 0.f, v2 = 0.f;
#pragma unroll
    for (int i = 0; i < 8; i++) { v1 += t[i]; v2 = fmaf(t[i], t[i], v2); }
#pragma unroll
    for (int o = 16; o > 0; o >>= 1) {
        v1 += __shfl_xor_sync(0xffffffffu, v1, o);
        v2 += __shfl_xor_sync(0xffffffffu, v2, o);
    }
    float mean = v1 * (1.f/DM);
    float var  = v2 * (1.f/DM) - mean*mean;
    float rs = rsqrtf(var + 1e-5f);

    float4 g0 = *(const float4*)(gamma + col);
    float4 g1 = *(const float4*)(gamma + col + 4);
    float4 b0 = *(const float4*)(beta  + col);
    float4 b1 = *(const float4*)(beta  + col + 4);

    float4 r0, r1;
    r0.x = (t[0]-mean)*rs*g0.x + b0.x;
    r0.y = (t[1]-mean)*rs*g0.y + b0.y;
    r0.z = (t[2]-mean)*rs*g0.z + b0.z;
    r0.w = (t[3]-mean)*rs*g0.w + b0.w;
    r1.x = (t[4]-mean)*rs*g1.x + b1.x;
    r1.y = (t[5]-mean)*rs*g1.y + b1.y;
    r1.z = (t[6]-mean)*rs*g1.z + b1.z;
    r1.w = (t[7]-mean)*rs*g1.w + b1.w;

    float4* out4 = (float4*)(g_h + (size_t)bl*DM + col);
    out4[0] = r0;
    out4[1] = r1;
}

// ---------------- Mean pool ----------------
__global__ void pool_kernel() {
    int b = blockIdx.x;
    int m = threadIdx.x;
    float s = 0.f;
    for (int l = 0; l < LSEQ; l++)
        s += g_h[(size_t)((b << 10) + l)*DM + m];
    g_pooled[b*DM + m] = s * (1.f/LSEQ);
}

// ---------------- Decoder ----------------
__global__ void dec_kernel(const float* __restrict__ w,
                           const float* __restrict__ bb,
                           float* __restrict__ out) {
    int i = threadIdx.x;
    if (i < BSZ*10) {
        int b = i / 10, o = i % 10;
        float acc = bb[o];
#pragma unroll 8
        for (int m = 0; m < DM; m++)
            acc = fmaf(g_pooled[b*DM + m], w[m*10 + o], acc);
        out[i] = acc;
    }
}

// ---------------- Launch ----------------
extern "C" void kernel_launch(void* const* d_in, const int* in_sizes, int n_in,
                              void* d_out, int out_size) {
    const float* x         = (const float*)d_in[0];
    const float* enc_w     = (const float*)d_in[1];
    const float* enc_b     = (const float*)d_in[2];
    const float* in_proj_w = (const float*)d_in[3];
    const float* conv_w    = (const float*)d_in[4];
    const float* conv_b    = (const float*)d_in[5];
    const float* x_proj_w  = (const float*)d_in[6];
    const float* dt_w      = (const float*)d_in[7];
    const float* dt_b      = (const float*)d_in[8];
    const float* A_log     = (const float*)d_in[9];
    const float* Dv        = (const float*)d_in[10];
    const float* out_proj_w= (const float*)d_in[11];
    const float* ln_g      = (const float*)d_in[12];
    const float* ln_b      = (const float*)d_in[13];
    const float* dec_w     = (const float*)d_in[14];
    const float* dec_b     = (const float*)d_in[15];

    float *p_h, *p_xz, *p_proj, *p_ymod, *p_out2;
    cudaGetSymbolAddress((void**)&p_h,    g_h);
    cudaGetSymbolAddress((void**)&p_xz,   g_xz);
    cudaGetSymbolAddress((void**)&p_proj, g_proj);
    cudaGetSymbolAddress((void**)&p_ymod, g_ymod);
    cudaGetSymbolAddress((void**)&p_out2, g_out2);

    enc_kernel<<<MROWS, DM>>>(x, enc_w, enc_b);

    for (int i = 0; i < NL; i++) {
        // xz = h @ in_proj_w[i]   (8192x256 @ 256x1024)
        gemm_tf32_cp<128><<<dim3((2*DI)/64, MROWS/128), 256>>>(
            p_h, in_proj_w + (size_t)i*DM*2*DI, p_xz, MROWS, 2*DI, DM);

        // proj = silu(conv(xz_x)) @ x_proj_w[i]  (conv fused into A staging)
        xproj_conv_gemm<<<dim3(1, MROWS/64), 256>>>(
            p_xz, x_proj_w + (size_t)i*DI*PROJC, p_proj,
            conv_w + (size_t)i*DI*4, conv_b + (size_t)i*DI);

        // fused conv + dt + scan (lean serial loop)
        scan_kernel<<<BSZ*32, 256>>>(A_log + (size_t)i*DI*NST, Dv + (size_t)i*DI,
                                     dt_w + (size_t)i*DTR*DI, dt_b + (size_t)i*DI,
                                     conv_w + (size_t)i*DI*4, conv_b + (size_t)i*DI);

        // out2 = ymod @ out_proj_w[i]  (8192x512 @ 512x256)
        gemm_tf32_cp<128><<<dim3(DM/64, MROWS/128), 256>>>(
            p_ymod, out_proj_w + (size_t)i*DI*DM, p_out2, MROWS, DM, DI);

        // h = layernorm(out2 + h)
        ln_kernel<<<MROWS/16, 512>>>(ln_g + (size_t)i*DM, ln_b + (size_t)i*DM);
    }

    pool_kernel<<<BSZ, DM>>>();
    dec_kernel<<<1, 128>>>(dec_w, dec_b, (float*)d_out);
}

// round 14
// speedup vs baseline: 1.5266x; 1.2095x over previous
#include <cuda_runtime.h>
#include <cuda_bf16.h>
#include <math.h>

// ---------------- Problem dims ----------------
#define NL    8
#define BSZ   8
#define LSEQ  1024
#define DM    256
#define DI    512
#define NST   16
#define DTR   16
#define PROJC 48
#define MROWS (BSZ*LSEQ)  // 8192

// ---------------- Device scratch ----------------
__device__ float g_h   [MROWS*DM];
__device__ float g_xz  [MROWS*2*DI];
__device__ float g_proj[MROWS*PROJC];
__device__ float g_ymod[MROWS*DI];
__device__ float g_out2[MROWS*DM];
__device__ float g_pooled[BSZ*DM];

// ---------------- helpers ----------------
__device__ __forceinline__ void mma_tf32(float& d0, float& d1, float& d2, float& d3,
                                         unsigned a0, unsigned a1, unsigned a2, unsigned a3,
                                         unsigned b0, unsigned b1) {
    asm volatile(
        "mma.sync.aligned.m16n8k8.row.col.f32.tf32.tf32.f32 "
        "{%0,%1,%2,%3}, {%4,%5,%6,%7}, {%8,%9}, {%0,%1,%2,%3};\n"
        : "+f"(d0), "+f"(d1), "+f"(d2), "+f"(d3)
        : "r"(a0), "r"(a1), "r"(a2), "r"(a3), "r"(b0), "r"(b1));
}
__device__ __forceinline__ void cp16(unsigned dst, const void* src) {
    asm volatile("cp.async.cg.shared.global [%0], [%1], 16;\n" :: "r"(dst), "l"(src));
}
__device__ __forceinline__ void cp_commit() { asm volatile("cp.async.commit_group;\n"); }
__device__ __forceinline__ void cp_wait0()  { asm volatile("cp.async.wait_group 0;\n"); }
__device__ __forceinline__ void cp_wait1()  { asm volatile("cp.async.wait_group 1;\n"); }
__device__ __forceinline__ void cp_wait2()  { asm volatile("cp.async.wait_group 2;\n"); }

// ---------------- Encoder ----------------
__global__ void enc_kernel(const float* __restrict__ x,
                           const float* __restrict__ w,
                           const float* __restrict__ bb) {
    int bl = blockIdx.x;
    int m  = threadIdx.x;
    int b = bl >> 10, l = bl & 1023;
    float acc = bb[m];
#pragma unroll
    for (int c = 0; c < 3; c++)
        acc = fmaf(x[(b*3 + c)*LSEQ + l], w[c*DM + m], acc);
    g_h[bl*DM + m] = acc;
}

// ---------------- TF32 GEMM, cp.async 4-stage pipeline (in_proj / out_proj) -------
#define ASTR 20
#define BSTR 72
template<int BM>
__global__ void __launch_bounds__(256, 2)
gemm_tf32_cp(const float* __restrict__ A,
             const float* __restrict__ B,
             float* __restrict__ C,
             int M, int N, int K) {
    constexpr int AM = BM / 64;
    __shared__ unsigned As[4][BM*ASTR];
    __shared__ unsigned Bs[4][16*BSTR];

    const int tid  = threadIdx.x;
    const int lane = tid & 31;
    const int wid  = tid >> 5;
    const int wm   = wid & 3;
    const int wn   = wid >> 2;
    const int m0   = blockIdx.y * BM;
    const int n0   = blockIdx.x * 64;
    const int r = lane >> 2;
    const int c = lane & 3;

    const int bRow = tid >> 4;
    const int bNq  = tid & 15;
    const bool bOk = (n0 + bNq*4 + 3) < N;

    unsigned aBase[4], bBase[4];
#pragma unroll
    for (int s = 0; s < 4; s++) {
        aBase[s] = (unsigned)__cvta_generic_to_shared(&As[s][0]);
        bBase[s] = (unsigned)__cvta_generic_to_shared(&Bs[s][0]);
    }

    auto loadTile = [&](int t, int s) {
        int k0 = t * 16;
#pragma unroll
        for (int j = 0; j < AM; j++) {
            int slot = j*256 + tid;
            int row = slot >> 2, kq = slot & 3;
            cp16(aBase[s] + (row*ASTR + kq*4)*4,
                 A + (size_t)(m0 + row)*K + k0 + kq*4);
        }
        if (bOk)
            cp16(bBase[s] + (bRow*BSTR + bNq*4)*4,
                 B + (size_t)(k0 + bRow)*N + n0 + bNq*4);
        cp_commit();
    };

    float acc[AM][4][4] = {};
    const int T = K >> 4;

    loadTile(0, 0); loadTile(1, 1); loadTile(2, 2);

    for (int t = 0; t < T; t++) {
        int cur = t & 3;
        cp_wait2();
        __syncthreads();
        if (t + 3 < T) loadTile(t + 3, (t + 3) & 3);
        else           cp_commit();

        const unsigned* Ab = As[cur];
        const unsigned* Bb = Bs[cur];
#pragma unroll
        for (int kk = 0; kk < 16; kk += 8) {
            unsigned af[AM][4], bf[4][2];
#pragma unroll
            for (int am = 0; am < AM; am++) {
                int mrow = wm*(BM/4) + am*16;
                af[am][0] = Ab[(mrow + r    )*ASTR + kk + c    ];
                af[am][1] = Ab[(mrow + r + 8)*ASTR + kk + c    ];
                af[am][2] = Ab[(mrow + r    )*ASTR + kk + c + 4];
                af[am][3] = Ab[(mrow + r + 8)*ASTR + kk + c + 4];
            }
#pragma unroll
            for (int bn = 0; bn < 4; bn++) {
                int ncol = wn*32 + bn*8 + r;
                bf[bn][0] = Bb[(kk + c    )*BSTR + ncol];
                bf[bn][1] = Bb[(kk + c + 4)*BSTR + ncol];
            }
#pragma unroll
            for (int am = 0; am < AM; am++)
#pragma unroll
                for (int bn = 0; bn < 4; bn++)
                    mma_tf32(acc[am][bn][0], acc[am][bn][1], acc[am][bn][2], acc[am][bn][3],
                             af[am][0], af[am][1], af[am][2], af[am][3],
                             bf[bn][0], bf[bn][1]);
        }
    }

#pragma unroll
    for (int am = 0; am < AM; am++) {
#pragma unroll
        for (int bn = 0; bn < 4; bn++) {
            int m = m0 + wm*(BM/4) + am*16 + r;
            int n = n0 + wn*32 + bn*8 + 2*c;
            if (n + 1 < N) {
                *(float2*)(C + (size_t)m*N + n)       = make_float2(acc[am][bn][0], acc[am][bn][1]);
                *(float2*)(C + (size_t)(m + 8)*N + n) = make_float2(acc[am][bn][2], acc[am][bn][3]);
            } else if (n < N) {
                C[(size_t)m*N + n]       = acc[am][bn][0];
                C[(size_t)(m + 8)*N + n] = acc[am][bn][2];
            }
        }
    }
}

// ---------------- x_proj GEMM with fused conv+SiLU on the A path ----------------
#define RSTR 20
__global__ void __launch_bounds__(256)
xproj_conv_gemm(const float* __restrict__ xz,
                const float* __restrict__ W,
                float* __restrict__ Cout,
                const float* __restrict__ cw,
                const float* __restrict__ cb) {
    __shared__ unsigned As[64*RSTR];
    __shared__ float    Raw[3][67*RSTR];
    __shared__ unsigned Bs[3][16*BSTR];
    __shared__ float    scw[DI*4];
    __shared__ float    scb[DI];

    const int tid  = threadIdx.x;
    const int lane = tid & 31;
    const int wid  = tid >> 5;
    const int wm   = wid & 3;
    const int wn   = wid >> 2;
    const int m0   = blockIdx.y * 64;
    const int r = lane >> 2;
    const int c = lane & 3;

    for (int i = tid; i < 3*16*BSTR; i += 256) (&Bs[0][0])[i] = 0u;
    for (int i = tid; i < DI*4; i += 256) scw[i] = cw[i];
    for (int i = tid; i < DI;   i += 256) scb[i] = cb[i];
    const bool hz = (m0 & 1023) == 0;
    if (hz) {
#pragma unroll
        for (int s = 0; s < 3; s++)
            if (tid < 48) Raw[s][(tid >> 4)*RSTR + (tid & 15)] = 0.f;
    }
    __syncthreads();

    const int i1 = tid >> 2, q1 = tid & 3;
    const int bRow = tid >> 4;
    const int bNq  = tid & 15;
    const bool bOk = bNq < 12;

    unsigned rawB[3], bsB[3];
#pragma unroll
    for (int s = 0; s < 3; s++) {
        rawB[s] = (unsigned)__cvta_generic_to_shared(&Raw[s][0]);
        bsB[s]  = (unsigned)__cvta_generic_to_shared(&Bs[s][0]);
    }

    auto loadT = [&](int t, int s) {
        int k0 = t * 16;
        if (!hz || i1 >= 3)
            cp16(rawB[s] + (i1*RSTR + q1*4)*4,
                 xz + (size_t)(m0 - 3 + i1)*(2*DI) + k0 + q1*4);
        if (tid < 12) {
            int i2 = 64 + (tid >> 2);
            cp16(rawB[s] + (i2*RSTR + (tid & 3)*4)*4,
                 xz + (size_t)(m0 - 3 + i2)*(2*DI) + k0 + (tid & 3)*4);
        }
        if (bOk)
            cp16(bsB[s] + (bRow*BSTR + bNq*4)*4,
                 W + (size_t)(k0 + bRow)*PROJC + bNq*4);
        cp_commit();
    };

    float acc[4][4] = {};
    const int T = DI >> 4;

    loadT(0, 0); loadT(1, 1);

    for (int t = 0; t < T; t++) {
        int cur = t % 3;
        cp_wait1();
        __syncthreads();
        if (t + 2 < T) loadT(t + 2, (t + 2) % 3);
        else           cp_commit();

        {
            const float* R = Raw[cur];
            int row = tid >> 2;
            int cb4 = (tid & 3) * 4;
#pragma unroll
            for (int j = 0; j < 4; j++) {
                int cc = cb4 + j;
                int d  = t*16 + cc;
                float a = scb[d];
#pragma unroll
                for (int k = 0; k < 4; k++)
                    a = fmaf(R[(row + k)*RSTR + cc], scw[d*4 + k], a);
                a = a / (1.f + __expf(-a));
                As[row*RSTR + cc] = __float_as_uint(a);
            }
        }
        __syncthreads();

        const unsigned* Bb = Bs[cur];
#pragma unroll
        for (int kk = 0; kk < 16; kk += 8) {
            unsigned af[4], bf[4][2];
            {
                int mrow = wm*16;
                af[0] = As[(mrow + r    )*RSTR + kk + c    ];
                af[1] = As[(mrow + r + 8)*RSTR + kk + c    ];
                af[2] = As[(mrow + r    )*RSTR + kk + c + 4];
                af[3] = As[(mrow + r + 8)*RSTR + kk + c + 4];
            }
#pragma unroll
            for (int bn = 0; bn < 4; bn++) {
                int ncol = wn*32 + bn*8 + r;
                bf[bn][0] = Bb[(kk + c    )*BSTR + ncol];
                bf[bn][1] = Bb[(kk + c + 4)*BSTR + ncol];
            }
#pragma unroll
            for (int bn = 0; bn < 4; bn++)
                mma_tf32(acc[bn][0], acc[bn][1], acc[bn][2], acc[bn][3],
                         af[0], af[1], af[2], af[3],
                         bf[bn][0], bf[bn][1]);
        }
    }

#pragma unroll
    for (int bn = 0; bn < 4; bn++) {
        int m = m0 + wm*16 + r;
        int n = wn*32 + bn*8 + 2*c;
        if (n + 1 < PROJC) {
            *(float2*)(Cout + (size_t)m*PROJC + n)       = make_float2(acc[bn][0], acc[bn][1]);
            *(float2*)(Cout + (size_t)(m + 8)*PROJC + n) = make_float2(acc[bn][2], acc[bn][3]);
        } else if (n < PROJC) {
            Cout[(size_t)m*PROJC + n]       = acc[bn][0];
            Cout[(size_t)(m + 8)*PROJC + n] = acc[bn][2];
        }
    }
}

// ---------------- Fused conv + dt + scan, transpose-reduce ----------------
// Block = 256 thr = 16 halfwarp channels. SCH=64 chunks.
// Serial loop: state update + STS of p=state*C into per-warp psh tile.
// Every 16 steps: warp-local transpose reduce (4x LDS.128 + tree sum) -> y.
#define SCH 64
#define SPSTR 52
#define PSTR 36          // per-l stride in psh (16B aligned, conflict-free)
__global__ void __launch_bounds__(256)
scan_kernel(const float* __restrict__ A_log,
            const float* __restrict__ Dv,
            const float* __restrict__ dtw,
            const float* __restrict__ dtb,
            const float* __restrict__ cw,
            const float* __restrict__ cb) {
    __shared__ float sp[2][SCH*SPSTR];   // proj rows        26.6 KB
    __shared__ float rx[2][67*16];       // raw x + halo      8.6 KB
    __shared__ float sz[2][SCH*16];      // raw z             8.2 KB
    __shared__ float su2[SCH*16];        // u; reused as y    4.1 KB
    __shared__ float sgg[SCH*32];        // gate, u*D*gate    8.2 KB
    __shared__ float psh[8*16*PSTR];     // p transpose tile 18.4 KB
    __shared__ float sDv[16];

    const int b  = blockIdx.x >> 5;
    const int d0 = (blockIdx.x & 31) * 16;
    const int tid = threadIdx.x;
    const int hw = tid >> 4;
    const int n  = tid & 15;
    const int lane = tid & 31;
    const int wid  = tid >> 5;
    const int d  = d0 + hw;
    const int hbase = lane & 16;
    const int blbase = b << 10;

    const int rl = tid >> 2;
    const int rq = tid & 3;

    // conv weights for this thread's 4 convert columns
    const int ccol = (tid & 3) * 4;
    float wv[4][4], bv[4];
#pragma unroll
    for (int j = 0; j < 4; j++) {
        bv[j] = cb[d0 + ccol + j];
#pragma unroll
        for (int k = 0; k < 4; k++)
            wv[j][k] = cw[(d0 + ccol + j)*4 + k];
    }
    if (tid < 16) sDv[tid] = Dv[d0 + tid];
    if (tid < 48) rx[0][tid] = 0.f;   // chunk-0 halo

    unsigned spB[2], rxB[2], szB[2];
#pragma unroll
    for (int s = 0; s < 2; s++) {
        spB[s] = (unsigned)__cvta_generic_to_shared(&sp[s][0]);
        rxB[s] = (unsigned)__cvta_generic_to_shared(&rx[s][0]);
        szB[s] = (unsigned)__cvta_generic_to_shared(&sz[s][0]);
    }

    auto loadChunk = [&](int c0, int buf) {
        cp16(rxB[buf] + (rl*16 + rq*4)*4,
             g_xz + (size_t)(blbase + c0 - 3 + rl)*(2*DI) + d0 + rq*4);
        if (tid < 12) {
            int i2 = 64 + (tid >> 2);
            cp16(rxB[buf] + (i2*16 + (tid & 3)*4)*4,
                 g_xz + (size_t)(blbase + c0 - 3 + i2)*(2*DI) + d0 + (tid & 3)*4);
        }
        cp16(szB[buf] + (rl*16 + rq*4)*4,
             g_xz + (size_t)(blbase + c0 + rl)*(2*DI) + DI + d0 + rq*4);
#pragma unroll
        for (int k = 0; k < 3; k++) {
            int s = tid + k*256;
            int l = s / 12, q = s - l*12;
            cp16(spB[buf] + (l*SPSTR + q*4)*4,
                 g_proj + (size_t)(blbase + c0 + l)*PROJC + q*4);
        }
        cp_commit();
    };
    auto loadChunk0 = [&]() {
        if (rl >= 3)
            cp16(rxB[0] + (rl*16 + rq*4)*4,
                 g_xz + (size_t)(blbase - 3 + rl)*(2*DI) + d0 + rq*4);
        if (tid < 12) {
            int i2 = 64 + (tid >> 2);
            cp16(rxB[0] + (i2*16 + (tid & 3)*4)*4,
                 g_xz + (size_t)(blbase - 3 + i2)*(2*DI) + d0 + (tid & 3)*4);
        }
        cp16(szB[0] + (rl*16 + rq*4)*4,
             g_xz + (size_t)(blbase + rl)*(2*DI) + DI + d0 + rq*4);
#pragma unroll
        for (int k = 0; k < 3; k++) {
            int s = tid + k*256;
            int l = s / 12, q = s - l*12;
            cp16(spB[0] + (l*SPSTR + q*4)*4,
                 g_proj + (size_t)(blbase + l)*PROJC + q*4);
        }
        cp_commit();
    };

    float wdt[DTR];
#pragma unroll
    for (int r = 0; r < DTR; r++) wdt[r] = dtw[r*DI + d];
    const float dtbv = dtb[d];
    const float Ad = -__expf(A_log[d*NST + n]);
    float state = 0.f;

    float* psw = &psh[wid*16*PSTR];

    loadChunk0();

    for (int cc = 0; cc < LSEQ/SCH; cc++) {
        int buf = cc & 1;
        if (cc + 1 < LSEQ/SCH) { loadChunk((cc+1)*SCH, buf ^ 1); cp_wait1(); }
        else                   { cp_wait0(); }
        __syncthreads();

        const float* P = sp[buf];
        const float* X = rx[buf];
        const float* Z = sz[buf];

        // dt for steps {j*16+n}
        float dtv4[4];
#pragma unroll
        for (int j = 0; j < 4; j++) {
            float a = dtbv;
            const float* row = &P[(j*16 + n)*SPSTR];
#pragma unroll
            for (int r = 0; r < DTR; r++) a = fmaf(row[r], wdt[r], a);
            dtv4[j] = (a > 20.f) ? a : __logf(1.f + __expf(a));
        }

        // convert: u, gate, g2 = u*D*gate  (4 cols per thread at row rl)
#pragma unroll
        for (int j = 0; j < 4; j++) {
            int c2 = ccol + j;
            float a = bv[j];
#pragma unroll
            for (int k = 0; k < 4; k++)
                a = fmaf(X[(rl + k)*16 + c2], wv[j][k], a);
            float u = a / (1.f + __expf(-a));
            su2[rl*16 + c2] = u;
            float zz = Z[rl*16 + c2];
            float gate = zz / (1.f + __expf(-zz));
            sgg[rl*32 + c2*2    ] = gate;
            sgg[rl*32 + c2*2 + 1] = u * sDv[c2] * gate;
        }
        __syncthreads();

        // serial loop with transpose-reduce every 16 steps
#pragma unroll
        for (int g = 0; g < SCH/16; g++) {
#pragma unroll
            for (int i = 0; i < 16; i++) {
                int l = g*16 + i;
                float dtv = __shfl_sync(0xffffffffu, dtv4[l >> 4], hbase + (l & 15), 32);
                float uv  = su2[l*16 + hw];
                float Bv  = P[l*SPSTR + DTR + n];
                float Cv  = P[l*SPSTR + DTR + NST + n];
                state = fmaf(__expf(dtv*Ad), state, dtv*uv*Bv);
                psw[i*PSTR + lane] = state * Cv;
            }
            __syncwarp();
            {
                int lo = g*16;
                const float4* row = (const float4*)&psw[n*PSTR + hbase];
                float4 v0 = row[0], v1 = row[1], v2 = row[2], v3 = row[3];
                float s = (((v0.x+v0.y)+(v0.z+v0.w)) + ((v1.x+v1.y)+(v1.z+v1.w)))
                        + (((v2.x+v2.y)+(v2.z+v2.w)) + ((v3.x+v3.y)+(v3.z+v3.w)));
                float2 gg = *(const float2*)&sgg[(lo + n)*32 + hw*2];
                su2[(lo + n)*16 + hw] = fmaf(s, gg.x, gg.y);
            }
            __syncwarp();
        }
        __syncthreads();

        // coalesced writeback
        {
            float4 v = *(const float4*)&su2[rl*16 + rq*4];
            *(float4*)(g_ymod + (size_t)(blbase + cc*SCH + rl)*DI + d0 + rq*4) = v;
        }
    }
}

// ---------------- Residual add + LayerNorm: warp-per-row, float4 ----------------
__global__ void __launch_bounds__(512)
ln_kernel(const float* __restrict__ gamma,
          const float* __restrict__ beta) {
    int wid  = threadIdx.x >> 5;
    int lane = threadIdx.x & 31;
    int bl   = blockIdx.x * 16 + wid;
    int col  = lane * 8;

    const float4* o4 = (const float4*)(g_out2 + (size_t)bl*DM + col);
    const float4* h4 = (const float4*)(g_h    + (size_t)bl*DM + col);
    float t[8];
    float4 a = o4[0], b = h4[0];
    t[0]=a.x+b.x; t[1]=a.y+b.y; t[2]=a.z+b.z; t[3]=a.w+b.w;
    a = o4[1]; b = h4[1];
    t[4]=a.x+b.x; t[5]=a.y+b.y; t[6]=a.z+b.z; t[7]=a.w+b.w;

    float v1 = 0.f, v2 = 0.f;
#pragma unroll
    for (int i = 0; i < 8; i++) { v1 += t[i]; v2 = fmaf(t[i], t[i], v2); }
#pragma unroll
    for (int o = 16; o > 0; o >>= 1) {
        v1 += __shfl_xor_sync(0xffffffffu, v1, o);
        v2 += __shfl_xor_sync(0xffffffffu, v2, o);
    }
    float mean = v1 * (1.f/DM);
    float var  = v2 * (1.f/DM) - mean*mean;
    float rs = rsqrtf(var + 1e-5f);

    float4 g0 = *(const float4*)(gamma + col);
    float4 g1 = *(const float4*)(gamma + col + 4);
    float4 b0 = *(const float4*)(beta  + col);
    float4 b1 = *(const float4*)(beta  + col + 4);

    float4 r0, r1;
    r0.x = (t[0]-mean)*rs*g0.x + b0.x;
    r0.y = (t[1]-mean)*rs*g0.y + b0.y;
    r0.z = (t[2]-mean)*rs*g0.z + b0.z;
    r0.w = (t[3]-mean)*rs*g0.w + b0.w;
    r1.x = (t[4]-mean)*rs*g1.x + b1.x;
    r1.y = (t[5]-mean)*rs*g1.y + b1.y;
    r1.z = (t[6]-mean)*rs*g1.z + b1.z;
    r1.w = (t[7]-mean)*rs*g1.w + b1.w;

    float4* out4 = (float4*)(g_h + (size_t)bl*DM + col);
    out4[0] = r0;
    out4[1] = r1;
}

// ---------------- Mean pool ----------------
__global__ void pool_kernel() {
    int b = blockIdx.x;
    int m = threadIdx.x;
    float s = 0.f;
    for (int l = 0; l < LSEQ; l++)
        s += g_h[(size_t)((b << 10) + l)*DM + m];
    g_pooled[b*DM + m] = s * (1.f/LSEQ);
}

// ---------------- Decoder ----------------
__global__ void dec_kernel(const float* __restrict__ w,
                           const float* __restrict__ bb,
                           float* __restrict__ out) {
    int i = threadIdx.x;
    if (i < BSZ*10) {
        int b = i / 10, o = i % 10;
        float acc = bb[o];
#pragma unroll 8
        for (int m = 0; m < DM; m++)
            acc = fmaf(g_pooled[b*DM + m], w[m*10 + o], acc);
        out[i] = acc;
    }
}

// ---------------- Launch ----------------
extern "C" void kernel_launch(void* const* d_in, const int* in_sizes, int n_in,
                              void* d_out, int out_size) {
    const float* x         = (const float*)d_in[0];
    const float* enc_w     = (const float*)d_in[1];
    const float* enc_b     = (const float*)d_in[2];
    const float* in_proj_w = (const float*)d_in[3];
    const float* conv_w    = (const float*)d_in[4];
    const float* conv_b    = (const float*)d_in[5];
    const float* x_proj_w  = (const float*)d_in[6];
    const float* dt_w      = (const float*)d_in[7];
    const float* dt_b      = (const float*)d_in[8];
    const float* A_log     = (const float*)d_in[9];
    const float* Dv        = (const float*)d_in[10];
    const float* out_proj_w= (const float*)d_in[11];
    const float* ln_g      = (const float*)d_in[12];
    const float* ln_b      = (const float*)d_in[13];
    const float* dec_w     = (const float*)d_in[14];
    const float* dec_b     = (const float*)d_in[15];

    float *p_h, *p_xz, *p_proj, *p_ymod, *p_out2;
    cudaGetSymbolAddress((void**)&p_h,    g_h);
    cudaGetSymbolAddress((void**)&p_xz,   g_xz);
    cudaGetSymbolAddress((void**)&p_proj, g_proj);
    cudaGetSymbolAddress((void**)&p_ymod, g_ymod);
    cudaGetSymbolAddress((void**)&p_out2, g_out2);

    enc_kernel<<<MROWS, DM>>>(x, enc_w, enc_b);

    for (int i = 0; i < NL; i++) {
        // xz = h @ in_proj_w[i]   (8192x256 @ 256x1024)
        gemm_tf32_cp<128><<<dim3((2*DI)/64, MROWS/128), 256>>>(
            p_h, in_proj_w + (size_t)i*DM*2*DI, p_xz, MROWS, 2*DI, DM);

        // proj = silu(conv(xz_x)) @ x_proj_w[i]  (conv fused into A staging)
        xproj_conv_gemm<<<dim3(1, MROWS/64), 256>>>(
            p_xz, x_proj_w + (size_t)i*DI*PROJC, p_proj,
            conv_w + (size_t)i*DI*4, conv_b + (size_t)i*DI);

        // fused conv + dt + scan (transpose-reduce)
        scan_kernel<<<BSZ*32, 256>>>(A_log + (size_t)i*DI*NST, Dv + (size_t)i*DI,
                                     dt_w + (size_t)i*DTR*DI, dt_b + (size_t)i*DI,
                                     conv_w + (size_t)i*DI*4, conv_b + (size_t)i*DI);

        // out2 = ymod @ out_proj_w[i]  (8192x512 @ 512x256)
        gemm_tf32_cp<128><<<dim3(DM/64, MROWS/128), 256>>>(
            p_ymod, out_proj_w + (size_t)i*DI*DM, p_out2, MROWS, DM, DI);

        // h = layernorm(out2 + h)
        ln_kernel<<<MROWS/16, 512>>>(ln_g + (size_t)i*DM, ln_b + (size_t)i*DM);
    }

    pool_kernel<<<BSZ, DM>>>();
    dec_kernel<<<1, 128>>>(dec_w, dec_b, (float*)d_out);
}